// round 1
// baseline (speedup 1.0000x reference)
#include <cuda_runtime.h>
#include <cuda_bf16.h>

// WindowAttention fused kernel, fp32 baseline.
// One CTA per batch element b in [0, 4096). w = b % 64 selects window mask + ids_keep row.
// Pipeline in shared memory: load x -> qkv gemm -> q@k^T + bias + mask -> softmax
//                            -> attn@v -> proj gemm -> out.

#define NTOK 25
#define DIM  128
#define NH   4
#define HD   32
#define NWIN 64
#define WSQ  49

__global__ __launch_bounds__(256, 1)
void win_attn_kernel(const float* __restrict__ x,
                     const float* __restrict__ mask,
                     const int*   __restrict__ ids_keep,
                     const float* __restrict__ qkv_w,
                     const float* __restrict__ qkv_b,
                     const float* __restrict__ proj_w,
                     const float* __restrict__ proj_b,
                     const float* __restrict__ bias_table,
                     const int*   __restrict__ rel_index,
                     float* __restrict__ out)
{
    extern __shared__ float sm[];
    float* xs  = sm;            // 3200 floats: x tile, later reused as attention output
    float* qs  = sm + 3200;     // [h][n][d]  : (h*25+n)*32 + d   (q, pre-scaled)
    float* ks  = sm + 6400;     // [h][d][m]  : h*800 + d*25 + m
    float* vs  = sm + 9600;     // [h][m][d]  : h*800 + m*32 + d
    float* at  = sm + 12800;    // [h][n][m]  : (h*25+n)*25 + m  (2500 floats)
    int*   ids = (int*)(sm + 15300);  // 25 ints

    const int b = blockIdx.x;
    const int w = b & (NWIN - 1);
    const int t = threadIdx.x;

    // ---- load x tile + ids ----
    const float* xb = x + (size_t)b * (NTOK * DIM);
    for (int i = t; i < NTOK * DIM; i += 256) xs[i] = xb[i];
    if (t < NTOK) ids[t] = ids_keep[w * NTOK + t];
    __syncthreads();

    // ---- QKV gemm: (25,128) @ (128,384)^T + bias ----
    const float scale = 0.17677669529663687f;  // 1/sqrt(32)
    for (int j = t; j < 3 * DIM; j += 256) {
        float acc[NTOK];
        const float bj = qkv_b[j];
        #pragma unroll
        for (int i = 0; i < NTOK; i++) acc[i] = bj;
        const float4* wr = (const float4*)(qkv_w + j * DIM);
        for (int kk = 0; kk < DIM / 4; kk++) {
            const float4 wv = __ldg(&wr[kk]);
            #pragma unroll
            for (int i = 0; i < NTOK; i++) {
                const float4 xv = *(const float4*)(xs + i * DIM + kk * 4);
                acc[i] = fmaf(xv.x, wv.x, acc[i]);
                acc[i] = fmaf(xv.y, wv.y, acc[i]);
                acc[i] = fmaf(xv.z, wv.z, acc[i]);
                acc[i] = fmaf(xv.w, wv.w, acc[i]);
            }
        }
        const int part = j >> 7, jj = j & 127, h = jj >> 5, d = jj & 31;
        if (part == 0) {
            #pragma unroll
            for (int i = 0; i < NTOK; i++) qs[(h * NTOK + i) * HD + d] = acc[i] * scale;
        } else if (part == 1) {
            #pragma unroll
            for (int i = 0; i < NTOK; i++) ks[h * 800 + d * NTOK + i] = acc[i];
        } else {
            #pragma unroll
            for (int i = 0; i < NTOK; i++) vs[h * 800 + i * HD + d] = acc[i];
        }
    }
    __syncthreads();

    // ---- attention scores: q@k^T + rel-pos bias + window mask ----
    for (int e = t; e < NH * NTOK * NTOK; e += 256) {
        const int h = e / (NTOK * NTOK);
        const int r = e - h * (NTOK * NTOK);
        const int n = r / NTOK, m = r - n * NTOK;
        const float* qr = qs + (h * NTOK + n) * HD;
        const float* kr = ks + h * 800 + m;
        float a = 0.f;
        #pragma unroll
        for (int d = 0; d < HD; d++) a = fmaf(qr[d], kr[d * NTOK], a);
        const int in_ = ids[n], im = ids[m];
        const int ridx = rel_index[in_ * WSQ + im];
        a += bias_table[ridx * NH + h] + mask[w * (WSQ * WSQ) + in_ * WSQ + im];
        at[e] = a;
    }
    __syncthreads();

    // ---- softmax over m (one thread per (h,n) row) ----
    if (t < NH * NTOK) {
        float* row = at + t * NTOK;
        float mx = row[0];
        #pragma unroll
        for (int m = 1; m < NTOK; m++) mx = fmaxf(mx, row[m]);
        float s = 0.f;
        #pragma unroll
        for (int m = 0; m < NTOK; m++) { const float ev = __expf(row[m] - mx); row[m] = ev; s += ev; }
        const float inv = 1.0f / s;
        #pragma unroll
        for (int m = 0; m < NTOK; m++) row[m] *= inv;
    }
    __syncthreads();

    // ---- attn @ v -> o (reuse xs) ----
    for (int e = t; e < NTOK * DIM; e += 256) {
        const int n = e >> 7, c = e & 127, h = c >> 5, d = c & 31;
        const float* ar = at + (h * NTOK + n) * NTOK;
        const float* vr = vs + h * 800 + d;
        float a = 0.f;
        #pragma unroll
        for (int m = 0; m < NTOK; m++) a = fmaf(ar[m], vr[m * HD], a);
        xs[e] = a;
    }
    __syncthreads();

    // ---- proj gemm: (25,128) @ (128,128)^T + bias ----
    {
        const int j = t & 127;
        const int ibase = (t < 128) ? 0 : 13;
        const int nrows = (t < 128) ? 13 : 12;
        float acc[13];
        const float pb = proj_b[j];
        #pragma unroll
        for (int i = 0; i < 13; i++) acc[i] = pb;
        const float4* wr = (const float4*)(proj_w + j * DIM);
        for (int kk = 0; kk < DIM / 4; kk++) {
            const float4 wv = __ldg(&wr[kk]);
            #pragma unroll
            for (int i = 0; i < 13; i++) {
                if (i < nrows) {
                    const float4 xv = *(const float4*)(xs + (ibase + i) * DIM + kk * 4);
                    acc[i] = fmaf(xv.x, wv.x, acc[i]);
                    acc[i] = fmaf(xv.y, wv.y, acc[i]);
                    acc[i] = fmaf(xv.z, wv.z, acc[i]);
                    acc[i] = fmaf(xv.w, wv.w, acc[i]);
                }
            }
        }
        float* ob = out + (size_t)b * (NTOK * DIM);
        for (int i = 0; i < nrows; i++) ob[(ibase + i) * DIM + j] = acc[i];
    }
}

extern "C" void kernel_launch(void* const* d_in, const int* in_sizes, int n_in,
                              void* d_out, int out_size)
{
    const float* x          = (const float*)d_in[0];
    const float* mask       = (const float*)d_in[1];
    const int*   ids_keep   = (const int*)  d_in[2];
    const float* qkv_w      = (const float*)d_in[3];
    const float* qkv_b      = (const float*)d_in[4];
    const float* proj_w     = (const float*)d_in[5];
    const float* proj_b     = (const float*)d_in[6];
    const float* bias_table = (const float*)d_in[7];
    const int*   rel_index  = (const int*)  d_in[8];

    const int smem_bytes = 15325 * 4;  // 61300 B
    cudaFuncSetAttribute(win_attn_kernel,
                         cudaFuncAttributeMaxDynamicSharedMemorySize, smem_bytes);
    win_attn_kernel<<<4096, 256, smem_bytes>>>(
        x, mask, ids_keep, qkv_w, qkv_b, proj_w, proj_b,
        bias_table, rel_index, (float*)d_out);
}

// round 2
// speedup vs baseline: 1.5778x; 1.5778x over previous
#include <cuda_runtime.h>
#include <cuda_bf16.h>

#define NTOK 25
#define DIM  128
#define NH   4
#define HD   32
#define NWIN 64
#define WSQ  49

// Transposed weight scratch (filled each launch by a prologue kernel).
__device__ float g_wT[DIM * 3 * DIM];   // [k][j]  k in [0,128), j in [0,384)
__device__ float g_pT[DIM * DIM];       // [k][j]  k in [0,128), j in [0,128)

__global__ void transpose_weights(const float* __restrict__ qkv_w,
                                  const float* __restrict__ proj_w)
{
    const int e = blockIdx.x * 256 + threadIdx.x;
    if (e < 3 * DIM * DIM) {
        const int j = e / DIM, kk = e % DIM;     // qkv_w row-major [j][k]
        g_wT[kk * (3 * DIM) + j] = qkv_w[e];
    }
    if (e < DIM * DIM) {
        const int j = e / DIM, kk = e % DIM;
        g_pT[kk * DIM + j] = proj_w[e];
    }
}

// ---- packed f32x2 helpers ----
__device__ __forceinline__ unsigned long long pack2(float lo, float hi) {
    unsigned long long r;
    asm("mov.b64 %0, {%1, %2};" : "=l"(r) : "f"(lo), "f"(hi));
    return r;
}
__device__ __forceinline__ float2 unpack2(unsigned long long v) {
    float2 r;
    asm("mov.b64 {%0, %1}, %2;" : "=f"(r.x), "=f"(r.y) : "l"(v));
    return r;
}
#define FMA2(d, a, b, c) \
    asm("fma.rn.f32x2 %0, %1, %2, %3;" : "=l"(d) : "l"(a), "l"(b), "l"(c))

// Shared layout (floats):
//   xT  [128][26]   0     .. 3328   (reused as oT after attn@v)
//   qs  [h][n][d]   3328  .. 6528   (pre-scaled q)
//   ks  [h][d][m]   6528  .. 9728
//   vs  [h][m][d]   9728  .. 12928
//   at  [h][n][m]   12928 .. 15428
//   ids (25 ints)   15428 .. 15453
#define SM_FLOATS 15456

__global__ __launch_bounds__(256, 3)
void win_attn_kernel(const float* __restrict__ x,
                     const float* __restrict__ mask,
                     const int*   __restrict__ ids_keep,
                     const float* __restrict__ qkv_b,
                     const float* __restrict__ proj_b,
                     const float* __restrict__ bias_table,
                     const int*   __restrict__ rel_index,
                     float* __restrict__ out)
{
    extern __shared__ float sm[];
    float* xT = sm;             // [k*26 + i], pad 26
    float* qs = sm + 3328;
    float* ks = sm + 6528;
    float* vs = sm + 9728;
    float* at = sm + 12928;
    int*  ids = (int*)(sm + 15428);

    const int b = blockIdx.x;
    const int w = b & (NWIN - 1);
    const int t = threadIdx.x;

    // ---- load x transposed + ids ----
    const float* xb = x + (size_t)b * (NTOK * DIM);
    for (int e = t; e < NTOK * DIM; e += 256) {
        const int i = e >> 7, kk = e & 127;
        xT[kk * 26 + i] = xb[e];
    }
    if (t < NTOK) ids[t] = ids_keep[w * NTOK + t];
    __syncthreads();

    // ---- QKV gemm: each thread computes 2 output columns (j=2t, 2t+1) for all 25 rows ----
    if (t < 192) {
        const int j0 = 2 * t;
        unsigned long long acc_a[12], acc_b[12];
        float a24, b24;
        {
            const float bja = qkv_b[j0], bjb = qkv_b[j0 + 1];
            #pragma unroll
            for (int p = 0; p < 12; p++) { acc_a[p] = pack2(bja, bja); acc_b[p] = pack2(bjb, bjb); }
            a24 = bja; b24 = bjb;
        }
        #pragma unroll 2
        for (int kk = 0; kk < DIM; kk++) {
            const float2 wv = *(const float2*)(g_wT + kk * 384 + j0);   // coalesced
            const unsigned long long w2a = pack2(wv.x, wv.x);
            const unsigned long long w2b = pack2(wv.y, wv.y);
            const float* xr = xT + kk * 26;
            #pragma unroll
            for (int p = 0; p < 12; p++) {
                const unsigned long long x2 = *(const unsigned long long*)(xr + 2 * p);
                FMA2(acc_a[p], x2, w2a, acc_a[p]);
                FMA2(acc_b[p], x2, w2b, acc_b[p]);
            }
            const float x24 = xr[24];
            a24 = fmaf(x24, wv.x, a24);
            b24 = fmaf(x24, wv.y, b24);
        }
        const float scale = 0.17677669529663687f; // 1/sqrt(32)
        #define STORE_COL(JX, ACC, A24)                                          \
        {                                                                        \
            const int part = (JX) >> 7, jj = (JX) & 127, h = jj >> 5, d = jj & 31; \
            if (part == 0) {                                                     \
                float* qp = qs + (h * 25) * 32 + d;                              \
                _Pragma("unroll")                                                \
                for (int p = 0; p < 12; p++) {                                   \
                    const float2 v = unpack2(ACC[p]);                            \
                    qp[(2 * p) * 32]     = v.x * scale;                          \
                    qp[(2 * p + 1) * 32] = v.y * scale;                          \
                }                                                                \
                qp[24 * 32] = (A24) * scale;                                     \
            } else if (part == 1) {                                              \
                float* kp = ks + h * 800 + d * 25;                               \
                _Pragma("unroll")                                                \
                for (int p = 0; p < 12; p++) {                                   \
                    const float2 v = unpack2(ACC[p]);                            \
                    kp[2 * p] = v.x; kp[2 * p + 1] = v.y;                        \
                }                                                                \
                kp[24] = (A24);                                                  \
            } else {                                                             \
                float* vp = vs + h * 800 + d;                                    \
                _Pragma("unroll")                                                \
                for (int p = 0; p < 12; p++) {                                   \
                    const float2 v = unpack2(ACC[p]);                            \
                    vp[(2 * p) * 32]     = v.x;                                  \
                    vp[(2 * p + 1) * 32] = v.y;                                  \
                }                                                                \
                vp[24 * 32] = (A24);                                             \
            }                                                                    \
        }
        STORE_COL(j0,     acc_a, a24)
        STORE_COL(j0 + 1, acc_b, b24)
        #undef STORE_COL
    }
    __syncthreads();

    // ---- attention scores: q@k^T + rel-pos bias + window mask ----
    for (int e = t; e < NH * NTOK * NTOK; e += 256) {
        const int h = e / (NTOK * NTOK);
        const int r = e - h * (NTOK * NTOK);
        const int n = r / NTOK, m = r - n * NTOK;
        const float* qr = qs + (h * NTOK + n) * HD;
        const float* kr = ks + h * 800 + m;
        float a = 0.f;
        #pragma unroll
        for (int d = 0; d < HD; d++) a = fmaf(qr[d], kr[d * 25], a);
        const int in_ = ids[n], im = ids[m];
        const int ridx = rel_index[in_ * WSQ + im];
        a += bias_table[ridx * NH + h] + mask[w * (WSQ * WSQ) + in_ * WSQ + im];
        at[e] = a;
    }
    __syncthreads();

    // ---- softmax over m ----
    if (t < NH * NTOK) {
        float* row = at + t * NTOK;
        float mx = row[0];
        #pragma unroll
        for (int m = 1; m < NTOK; m++) mx = fmaxf(mx, row[m]);
        float s = 0.f;
        #pragma unroll
        for (int m = 0; m < NTOK; m++) { const float ev = __expf(row[m] - mx); row[m] = ev; s += ev; }
        const float inv = 1.0f / s;
        #pragma unroll
        for (int m = 0; m < NTOK; m++) row[m] *= inv;
    }
    __syncthreads();

    // ---- attn @ v -> oT[c][n] (reuses xT buffer) ----
    float* oT = xT;
    for (int e = t; e < NTOK * DIM; e += 256) {
        const int n = e >> 7, c = e & 127, h = c >> 5, d = c & 31;
        const float* ar = at + (h * NTOK + n) * NTOK;
        const float* vr = vs + h * 800 + d;
        float a = 0.f;
        #pragma unroll
        for (int m = 0; m < NTOK; m++) a = fmaf(ar[m], vr[m * HD], a);
        oT[c * 26 + n] = a;
    }
    __syncthreads();

    // ---- proj gemm: thread j computes out[:, j], packed row-pairs ----
    if (t < DIM) {
        const int j = t;
        unsigned long long acc[12];
        float a24;
        {
            const float pb = proj_b[j];
            #pragma unroll
            for (int p = 0; p < 12; p++) acc[p] = pack2(pb, pb);
            a24 = pb;
        }
        #pragma unroll 2
        for (int c = 0; c < DIM; c++) {
            const float wv = g_pT[c * DIM + j];                 // coalesced
            const unsigned long long w2 = pack2(wv, wv);
            const float* orow = oT + c * 26;
            #pragma unroll
            for (int p = 0; p < 12; p++) {
                const unsigned long long x2 = *(const unsigned long long*)(orow + 2 * p);
                FMA2(acc[p], x2, w2, acc[p]);
            }
            a24 = fmaf(orow[24], wv, a24);
        }
        float* ob = out + (size_t)b * (NTOK * DIM) + j;
        #pragma unroll
        for (int p = 0; p < 12; p++) {
            const float2 v = unpack2(acc[p]);
            ob[(2 * p) * DIM]     = v.x;
            ob[(2 * p + 1) * DIM] = v.y;
        }
        ob[24 * DIM] = a24;
    }
}

extern "C" void kernel_launch(void* const* d_in, const int* in_sizes, int n_in,
                              void* d_out, int out_size)
{
    const float* x          = (const float*)d_in[0];
    const float* mask       = (const float*)d_in[1];
    const int*   ids_keep   = (const int*)  d_in[2];
    const float* qkv_w      = (const float*)d_in[3];
    const float* qkv_b      = (const float*)d_in[4];
    const float* proj_w     = (const float*)d_in[5];
    const float* proj_b     = (const float*)d_in[6];
    const float* bias_table = (const float*)d_in[7];
    const int*   rel_index  = (const int*)  d_in[8];

    transpose_weights<<<(3 * DIM * DIM + 255) / 256, 256>>>(qkv_w, proj_w);

    const int smem_bytes = SM_FLOATS * 4;
    cudaFuncSetAttribute(win_attn_kernel,
                         cudaFuncAttributeMaxDynamicSharedMemorySize, smem_bytes);
    win_attn_kernel<<<4096, 256, smem_bytes>>>(
        x, mask, ids_keep, qkv_b, proj_b, bias_table, rel_index, (float*)d_out);
}